// round 6
// baseline (speedup 1.0000x reference)
#include <cuda_runtime.h>
#include <cstdint>
#include <math.h>

#define NTOK 2048
#define HD   2048
#define NE   8
#define ID   1024
#define MAXPE 2048
#define KC   32
#define NSTAGE 4

__device__ int   g_count[NE];
__device__ int   g_tok[NE * MAXPE];
__device__ float g_wt [NE * MAXPE];
__device__ float g_act[(size_t)NE * MAXPE * ID];

// ---------------- helpers ----------------
__device__ __forceinline__ uint32_t smem_u32(const void* p) {
    uint32_t a;
    asm("{ .reg .u64 t; cvta.to.shared.u64 t, %1; cvt.u32.u64 %0, t; }" : "=r"(a) : "l"(p));
    return a;
}
#define STS128(v0, v1, v2, v3, a) \
    asm volatile("st.shared.v4.b32 [%0], {%1, %2, %3, %4};" :: "r"(a), "r"(v0), "r"(v1), "r"(v2), "r"(v3) : "memory")
#define MBAR_INIT(a, n) asm volatile("mbarrier.init.shared.b64 [%0], %1;" :: "r"(a), "r"(n) : "memory")
#define MBAR_ARRIVE(a)  asm volatile("mbarrier.arrive.shared.b64 _, [%0];" :: "r"(a) : "memory")
__device__ __forceinline__ void mbar_wait(uint32_t m, uint32_t ph) {
    uint32_t d = 0;
    asm volatile("{\n\t.reg .pred p;\n\tmbarrier.try_wait.parity.shared.b64 p, [%1], %2;\n\tselp.b32 %0,1,0,p;\n\t}"
                 : "=r"(d) : "r"(m), "r"(ph) : "memory");
    while (!d)
        asm volatile("{\n\t.reg .pred p;\n\tmbarrier.try_wait.parity.shared.b64 p, [%1], %2;\n\tselp.b32 %0,1,0,p;\n\t}"
                     : "=r"(d) : "r"(m), "r"(ph) : "memory");
}
__device__ __forceinline__ void cvt_hl(float a0, float a1, uint32_t& hi, uint32_t& lo) {
    uint32_t h;
    asm("cvt.rn.bf16x2.f32 %0, %1, %2;" : "=r"(h) : "f"(a1), "f"(a0));  // lo16=a0, hi16=a1
    float h0 = __uint_as_float(h << 16);
    float h1 = __uint_as_float(h & 0xFFFF0000u);
    uint32_t l;
    float l1 = a1 - h1, l0 = a0 - h0;
    asm("cvt.rn.bf16x2.f32 %0, %1, %2;" : "=r"(l) : "f"(l1), "f"(l0));
    hi = h; lo = l;
}
__device__ __forceinline__ void mma16816(float* c, const uint32_t* a, const uint32_t* b) {
    asm volatile("mma.sync.aligned.m16n8k16.row.col.f32.bf16.bf16.f32 "
        "{%0,%1,%2,%3}, {%4,%5,%6,%7}, {%8,%9}, {%0,%1,%2,%3};"
        : "+f"(c[0]), "+f"(c[1]), "+f"(c[2]), "+f"(c[3])
        : "r"(a[0]), "r"(a[1]), "r"(a[2]), "r"(a[3]), "r"(b[0]), "r"(b[1]));
}
__device__ __forceinline__ void ldsm4(uint32_t* r, uint32_t addr) {
    asm volatile("ldmatrix.sync.aligned.m8n8.x4.shared.b16 {%0,%1,%2,%3}, [%4];"
        : "=r"(r[0]), "=r"(r[1]), "=r"(r[2]), "=r"(r[3]) : "r"(addr));
}
__device__ __forceinline__ void ldsm4t(uint32_t* r, uint32_t addr) {
    asm volatile("ldmatrix.sync.aligned.m8n8.x4.trans.shared.b16 {%0,%1,%2,%3}, [%4];"
        : "=r"(r[0]), "=r"(r[1]), "=r"(r[2]), "=r"(r[3]) : "r"(addr));
}

// SMEM layout
#define ASTRIDE 80
#define BSTRIDE 272
#define SZ_A (128 * ASTRIDE)
#define SZ_B (32 * BSTRIDE)
#define OFF_AH 0
#define OFF_AL SZ_A
#define OFF_BH (2 * SZ_A)
#define OFF_BL (2 * SZ_A + SZ_B)
#define STAGE_SZ (2 * SZ_A + 2 * SZ_B)   // 37888
#define SM_TOK 0
#define SM_WT  512
#define SM_MBAR 1024                      // full[s] at +8s (s<4), empty[s] at +32+8s
#define SM_STAGE 1152
#define SMEM_SZ (SM_STAGE + NSTAGE * STAGE_SZ)   // 152704

// ---------------------------------------------------------------------------
__global__ void init_kernel(float4* __restrict__ out4) {
    int idx = blockIdx.x * blockDim.x + threadIdx.x;
    if (idx < NE) g_count[idx] = 0;
    if (idx < NTOK * HD / 4) out4[idx] = make_float4(0.f, 0.f, 0.f, 0.f);
}

// ---------------------------------------------------------------------------
__global__ void router_kernel(const float* __restrict__ x,
                              const float* __restrict__ gw) {
    int t = blockIdx.x, tid = threadIdx.x;
    float p[NE];
#pragma unroll
    for (int e = 0; e < NE; e++) p[e] = 0.f;
    const float* xr = x + (size_t)t * HD;
    for (int h = tid; h < HD; h += 256) {
        float xv = xr[h];
        const float* g = gw + (size_t)h * NE;
#pragma unroll
        for (int e = 0; e < NE; e++) p[e] = fmaf(xv, g[e], p[e]);
    }
#pragma unroll
    for (int e = 0; e < NE; e++)
#pragma unroll
        for (int o = 16; o > 0; o >>= 1)
            p[e] += __shfl_xor_sync(0xffffffffu, p[e], o);
    __shared__ float s[8][NE];
    int warp = tid >> 5, lane = tid & 31;
    if (lane == 0)
#pragma unroll
        for (int e = 0; e < NE; e++) s[warp][e] = p[e];
    __syncthreads();
    if (tid == 0) {
        float logit[NE];
#pragma unroll
        for (int e = 0; e < NE; e++) {
            float v = 0.f;
#pragma unroll
            for (int w = 0; w < 8; w++) v += s[w][e];
            logit[e] = v;
        }
        int i0 = 0;
#pragma unroll
        for (int e = 1; e < NE; e++) if (logit[e] > logit[i0]) i0 = e;
        int i1 = -1;
#pragma unroll
        for (int e = 0; e < NE; e++)
            if (e != i0 && (i1 < 0 || logit[e] > logit[i1])) i1 = e;
        float pr = expf(logit[i1] - logit[i0]);
        int p0 = atomicAdd(&g_count[i0], 1);
        g_tok[i0 * MAXPE + p0] = t; g_wt[i0 * MAXPE + p0] = 1.f / (1.f + pr);
        int p1 = atomicAdd(&g_count[i1], 1);
        g_tok[i1 * MAXPE + p1] = t; g_wt[i1 * MAXPE + p1] = pr / (1.f + pr);
    }
}

// ---------------------------------------------------------------------------
// Warp-specialized GEMM: tid<256 = 8 consumer warps (ldmatrix+mma),
// tid>=256 = 4 producer warps (LDG fp32 -> bf16 hi/lo -> STS), 4-stage ring.
// Staged layout & MMA schedule identical to the validated R5 kernel.
// ---------------------------------------------------------------------------
template <int NCHUNK, bool IL, int SEGMUL>
__device__ __forceinline__ void gemm_ws(
    const float* __restrict__ arow,   // producer threads: A row ptr (or null)
    const float* __restrict__ p0,     // producer: B base 0
    const float* __restrict__ p1,     // producer: B base 1
    int bkstride, uint32_t sb, float c[2][8][4])
{
    const int tid = threadIdx.x;
    if (tid < 256) {
        // ---- consumer ----
        const int lane = tid & 31, w = tid >> 5;
        const int wm = w & 3, wn = w >> 2;
        const int lrow8 = ((lane >> 3) & 1) * 8 + (lane & 7);
        const int lk16 = (lane & 16) ? 16 : 0;
        const uint32_t a_base = (uint32_t)(wm * 32 + lrow8) * ASTRIDE + lk16;
        const uint32_t b_base = (uint32_t)lrow8 * BSTRIDE + wn * 128 + lk16;
        int s = 0, par = 0;
#pragma unroll 1
        for (int ch = 0; ch < NCHUNK; ch++) {
            mbar_wait(sb + SM_MBAR + s * 8, par);
            uint32_t st = sb + SM_STAGE + s * STAGE_SZ;
#pragma unroll
            for (int sh = 0; sh < 2; sh++) {
                uint32_t ah[2][4], al[2][4], bh[8][2];
#pragma unroll
                for (int mt = 0; mt < 2; mt++) {
                    uint32_t ao = st + OFF_AH + a_base + mt * 16 * ASTRIDE + sh * 32;
                    ldsm4(ah[mt], ao);
                    ldsm4(al[mt], ao + (OFF_AL - OFF_AH));
                }
#pragma unroll
                for (int jp = 0; jp < 4; jp++) {
                    uint32_t r[4];
                    ldsm4t(r, st + OFF_BH + b_base + sh * 16 * BSTRIDE + jp * 32);
                    bh[2 * jp][0] = r[0]; bh[2 * jp][1] = r[1];
                    bh[2 * jp + 1][0] = r[2]; bh[2 * jp + 1][1] = r[3];
                }
#pragma unroll
                for (int mt = 0; mt < 2; mt++)
#pragma unroll
                    for (int j = 0; j < 8; j++) mma16816(c[mt][j], ah[mt], bh[j]);
#pragma unroll
                for (int mt = 0; mt < 2; mt++)
#pragma unroll
                    for (int j = 0; j < 8; j++) mma16816(c[mt][j], al[mt], bh[j]);
#pragma unroll
                for (int jp = 0; jp < 4; jp++) {
                    uint32_t r[4];
                    ldsm4t(r, st + OFF_BL + b_base + sh * 16 * BSTRIDE + jp * 32);
#pragma unroll
                    for (int mt = 0; mt < 2; mt++) {
                        mma16816(c[mt][2 * jp], ah[mt], r);
                        mma16816(c[mt][2 * jp + 1], ah[mt], r + 2);
                    }
                }
            }
            MBAR_ARRIVE(sb + SM_MBAR + 32 + s * 8);
            if (++s == NSTAGE) { s = 0; par ^= 1; }
        }
    } else {
        // ---- producer ----
        const int ptid = tid - 256;          // 0..127, = A row
        int s = 0, par = 0;
#pragma unroll 1
        for (int ch = 0; ch < NCHUNK; ch++) {
            const int k0 = ch * KC;
            float ar[32];
            if (arow) {
                const float4* p = (const float4*)(arow + k0);
#pragma unroll
                for (int i = 0; i < 8; i++) ((float4*)ar)[i] = p[i];
            } else {
#pragma unroll
                for (int i = 0; i < 32; i++) ar[i] = 0.f;
            }
            float bq0[2][8], bq1[2][8];
            int kk[2], sg[2];
#pragma unroll
            for (int t = 0; t < 2; t++) {
                int tsk = 2 * ptid + t;
                kk[t] = tsk >> 3; sg[t] = tsk & 7;
                const float* q0 = p0 + SEGMUL * sg[t] + (size_t)(k0 + kk[t]) * bkstride;
                const float* q1 = p1 + SEGMUL * sg[t] + (size_t)(k0 + kk[t]) * bkstride;
#pragma unroll
                for (int i = 0; i < 2; i++) {
                    ((float4*)bq0[t])[i] = ((const float4*)q0)[i];
                    ((float4*)bq1[t])[i] = ((const float4*)q1)[i];
                }
            }
            if (ch >= NSTAGE) mbar_wait(sb + SM_MBAR + 32 + s * 8, par ^ 1);
            uint32_t st = sb + SM_STAGE + s * STAGE_SZ;
            {
                uint32_t hi[16], lo[16];
#pragma unroll
                for (int i = 0; i < 16; i++) cvt_hl(ar[2 * i], ar[2 * i + 1], hi[i], lo[i]);
                uint32_t ad = st + OFF_AH + ptid * ASTRIDE;
                STS128(hi[0], hi[1], hi[2], hi[3], ad);
                STS128(hi[4], hi[5], hi[6], hi[7], ad + 16);
                STS128(hi[8], hi[9], hi[10], hi[11], ad + 32);
                STS128(hi[12], hi[13], hi[14], hi[15], ad + 48);
                ad += (OFF_AL - OFF_AH);
                STS128(lo[0], lo[1], lo[2], lo[3], ad);
                STS128(lo[4], lo[5], lo[6], lo[7], ad + 16);
                STS128(lo[8], lo[9], lo[10], lo[11], ad + 32);
                STS128(lo[12], lo[13], lo[14], lo[15], ad + 48);
            }
#pragma unroll
            for (int t = 0; t < 2; t++) {
                uint32_t bhi[8], blo[8];
#pragma unroll
                for (int i = 0; i < 8; i++) {
                    float fa, fb;
                    if (IL)         { fa = bq0[t][i];         fb = bq1[t][i]; }
                    else if (i < 4) { fa = bq0[t][2 * i];     fb = bq0[t][2 * i + 1]; }
                    else            { fa = bq1[t][2 * i - 8]; fb = bq1[t][2 * i - 7]; }
                    cvt_hl(fa, fb, bhi[i], blo[i]);
                }
                uint32_t bd = st + OFF_BH + kk[t] * BSTRIDE + sg[t] * 32;
                STS128(bhi[0], bhi[1], bhi[2], bhi[3], bd);
                STS128(bhi[4], bhi[5], bhi[6], bhi[7], bd + 16);
                bd += (OFF_BL - OFF_BH);
                STS128(blo[0], blo[1], blo[2], blo[3], bd);
                STS128(blo[4], blo[5], blo[6], blo[7], bd + 16);
            }
            MBAR_ARRIVE(sb + SM_MBAR + s * 8);
            if (++s == NSTAGE) { s = 0; par ^= 1; }
        }
    }
}

// ---------------------------------------------------------------------------
__global__ void __launch_bounds__(384, 1)
ffn1_mma(const float* __restrict__ x, const float* __restrict__ w13) {
    const int e = blockIdx.z;
    const int ne = g_count[e];
    const int row0 = blockIdx.x * 128;
    if (row0 >= ne) return;
    const int cbase = blockIdx.y * 64;

    extern __shared__ char smem[];
    uint32_t sb = smem_u32(smem);
    const int tid = threadIdx.x;
    if (tid < 128) {
        int r = row0 + tid;
        ((int*)(smem + SM_TOK))[tid] = (r < ne) ? g_tok[e * MAXPE + r] : -1;
    }
    if (tid == 0) {
#pragma unroll
        for (int s = 0; s < NSTAGE; s++) {
            MBAR_INIT(sb + SM_MBAR + s * 8, 128);
            MBAR_INIT(sb + SM_MBAR + 32 + s * 8, 256);
        }
    }
    __syncthreads();

    const float* we = w13 + (size_t)e * HD * (2 * ID);
    const float* p0 = we + cbase;
    const float* p1 = we + ID + cbase;
    const float* arow = nullptr;
    if (tid >= 256) {
        int tok = ((const int*)(smem + SM_TOK))[tid - 256];
        arow = (tok >= 0) ? (x + (size_t)tok * HD) : nullptr;
    }

    float c[2][8][4];
#pragma unroll
    for (int i = 0; i < 2; i++)
#pragma unroll
        for (int j = 0; j < 8; j++)
#pragma unroll
            for (int k = 0; k < 4; k++) c[i][j][k] = 0.f;

    gemm_ws<HD / KC, true, 8>(arow, p0, p1, 2 * ID, sb, c);

    if (tid < 256) {
        const int lane = tid & 31, w = tid >> 5, wm = w & 3, wn = w >> 2;
        const int g = lane >> 2, t = lane & 3;
#pragma unroll
        for (int mt = 0; mt < 2; mt++)
#pragma unroll
            for (int rr = 0; rr < 2; rr++) {
                int slot = row0 + wm * 32 + mt * 16 + rr * 8 + g;
                if (slot < ne) {
                    float* dst = g_act + ((size_t)(e * MAXPE) + slot) * ID + cbase + wn * 32;
#pragma unroll
                    for (int j = 0; j < 8; j++) {
                        float gg = c[mt][j][2 * rr], uu = c[mt][j][2 * rr + 1];
                        dst[j * 4 + t] = gg / (1.f + __expf(-gg)) * uu;
                    }
                }
            }
    }
}

// ---------------------------------------------------------------------------
__global__ void __launch_bounds__(384, 1)
ffn2_mma(const float* __restrict__ w2, float* __restrict__ out) {
    const int e = blockIdx.z;
    const int ne = g_count[e];
    const int row0 = blockIdx.x * 128;
    if (row0 >= ne) return;
    const int c0 = blockIdx.y * 128;

    extern __shared__ char smem[];
    uint32_t sb = smem_u32(smem);
    const int tid = threadIdx.x;
    if (tid < 128) {
        int r = row0 + tid;
        ((int*)(smem + SM_TOK))[tid]  = (r < ne) ? g_tok[e * MAXPE + r] : -1;
        ((float*)(smem + SM_WT))[tid] = (r < ne) ? g_wt[e * MAXPE + r] : 0.f;
    }
    if (tid == 0) {
#pragma unroll
        for (int s = 0; s < NSTAGE; s++) {
            MBAR_INIT(sb + SM_MBAR + s * 8, 128);
            MBAR_INIT(sb + SM_MBAR + 32 + s * 8, 256);
        }
    }
    __syncthreads();

    const float* p0 = w2 + (size_t)e * ID * HD + c0;
    const float* p1 = p0 + 8;
    const float* arow = nullptr;
    if (tid >= 256) {
        int r = row0 + (tid - 256);
        arow = (r < ne) ? (g_act + (size_t)(e * MAXPE + r) * ID) : nullptr;
    }

    float c[2][8][4];
#pragma unroll
    for (int i = 0; i < 2; i++)
#pragma unroll
        for (int j = 0; j < 8; j++)
#pragma unroll
            for (int k = 0; k < 4; k++) c[i][j][k] = 0.f;

    gemm_ws<ID / KC, false, 16>(arow, p0, p1, HD, sb, c);

    if (tid < 256) {
        const int lane = tid & 31, w = tid >> 5, wm = w & 3, wn = w >> 2;
        const int g = lane >> 2, t = lane & 3;
#pragma unroll
        for (int mt = 0; mt < 2; mt++)
#pragma unroll
            for (int rr = 0; rr < 2; rr++) {
                int rlocal = wm * 32 + mt * 16 + rr * 8 + g;
                int tok = ((const int*)(smem + SM_TOK))[rlocal];
                if (tok >= 0) {
                    float wt = ((const float*)(smem + SM_WT))[rlocal];
                    float* orow = out + (size_t)tok * HD + c0 + wn * 64;
#pragma unroll
                    for (int j = 0; j < 8; j++) {
                        atomicAdd(&orow[j * 8 + 2 * t],     wt * c[mt][j][2 * rr]);
                        atomicAdd(&orow[j * 8 + 2 * t + 1], wt * c[mt][j][2 * rr + 1]);
                    }
                }
            }
    }
}

// ---------------------------------------------------------------------------
extern "C" void kernel_launch(void* const* d_in, const int* in_sizes, int n_in,
                              void* d_out, int out_size) {
    const float* x   = (const float*)d_in[0];
    const float* gw  = (const float*)d_in[1];
    const float* w13 = (const float*)d_in[2];
    const float* w2  = (const float*)d_in[3];
    float* out = (float*)d_out;

    cudaFuncSetAttribute(ffn1_mma, cudaFuncAttributeMaxDynamicSharedMemorySize, SMEM_SZ);
    cudaFuncSetAttribute(ffn2_mma, cudaFuncAttributeMaxDynamicSharedMemorySize, SMEM_SZ);

    init_kernel<<<(NTOK * HD / 4 + 255) / 256, 256>>>((float4*)out);
    router_kernel<<<NTOK, 256>>>(x, gw);
    dim3 g1(MAXPE / 128, ID / 64, NE);    // (16, 16, 8)
    ffn1_mma<<<g1, 384, SMEM_SZ>>>(x, w13);
    dim3 g2(MAXPE / 128, HD / 128, NE);   // (16, 16, 8)
    ffn2_mma<<<g2, 384, SMEM_SZ>>>(w2, out);
}